// round 1
// baseline (speedup 1.0000x reference)
#include <cuda_runtime.h>

// YOLO loss, sm_103a.
// predictions: [B=128, NCH=255, S=26, S=26] f32   (d_in[0])
// targets:     [B=128, T=50, 5] f32                (d_in[1])
// out:         scalar f32 = loss / B
//
// Key insight: only channels {1..84} of box 0 at target cells (gather) and
// the 3 confidence channels {0, 85, 170} everywhere (coalesced) are needed.
// ~5 MB effective traffic instead of the 88 MB tensor.

#define S_GRID   26
#define NB_BOX   3
#define NCLS     80
#define NCH      255          // NB*(5+NCLS)
#define CELLS    (S_GRID * S_GRID)   // 676
#define BATCH_N  128
#define T_TGT    50
#define L_COORD  5.0f
#define L_NOOBJ  0.5f

__global__ void yolo_zero_out(float* out) { out[0] = 0.0f; }

__global__ __launch_bounds__(256)
void yolo_loss_kernel(const float* __restrict__ pred,
                      const float* __restrict__ tgt,
                      float* __restrict__ out)
{
    const int b    = blockIdx.x;
    const int tid  = threadIdx.x;
    const int lane = tid & 31;
    const int warp = tid >> 5;

    __shared__ float         s_tgt[T_TGT * 5];
    __shared__ unsigned char s_obj[CELLS];
    __shared__ float         s_warp[8];

    // stage targets + clear obj mask
    for (int i = tid; i < T_TGT * 5; i += 256) s_tgt[i] = tgt[b * T_TGT * 5 + i];
    for (int i = tid; i < CELLS; i += 256)     s_obj[i] = 0;
    __syncthreads();

    const float* predb = pred + (size_t)b * NCH * CELLS;

    float acc = 0.0f;

    // ---- per-target term: one warp per target, lanes stride channels 1..84 ----
    for (int t = warp; t < T_TGT; t += 8) {
        const float clsf = s_tgt[t * 5 + 0];
        const float cx   = s_tgt[t * 5 + 1];
        const float cy   = s_tgt[t * 5 + 2];

        int gx = (int)(cx * S_GRID);          // trunc == floor (cx >= 0)
        int gy = (int)(cy * S_GRID);
        const bool valid = (gx < S_GRID) && (gy < S_GRID);
        gx = min(max(gx, 0), S_GRID - 1);
        gy = min(max(gy, 0), S_GRID - 1);
        const int cell = gy * S_GRID + gx;

        if (lane == 0 && valid) s_obj[cell] = 1;   // idempotent; race-free

        const int clsi = (int)clsf;
        float sum = 0.0f;
        #pragma unroll
        for (int c = 1 + lane; c < 85; c += 32) {
            const float pv = predb[c * CELLS + cell];
            float tv, scale;
            if (c <= 4) {                      // coord: tgt[.,c] is cx,cy,w,h
                tv = s_tgt[t * 5 + c];
                scale = L_COORD;
            } else {                            // class one-hot
                tv = ((c - 5) == clsi) ? 1.0f : 0.0f;
                scale = 1.0f;
            }
            const float d = pv - tv;
            sum = fmaf(scale * d, d, sum);
        }
        #pragma unroll
        for (int off = 16; off; off >>= 1)
            sum += __shfl_down_sync(0xffffffffu, sum, off);
        if (lane == 0 && valid) acc += sum;
    }

    __syncthreads();   // obj mask complete before noobj sweep

    // ---- no-obj term: 3 conf channels, coalesced sweep of 2028 values ----
    float nsum = 0.0f;
    for (int i = tid; i < NB_BOX * CELLS; i += 256) {
        const int nb   = i / CELLS;
        const int cell = i - nb * CELLS;
        const float conf = predb[(nb * 85) * CELLS + cell];
        const bool isobj = (nb == 0) && s_obj[cell];
        if (!isobj) nsum = fmaf(conf, conf, nsum);
    }
    acc = fmaf(L_NOOBJ, nsum, acc);

    // ---- block reduce + atomic ----
    #pragma unroll
    for (int off = 16; off; off >>= 1)
        acc += __shfl_down_sync(0xffffffffu, acc, off);
    if (lane == 0) s_warp[warp] = acc;
    __syncthreads();
    if (warp == 0) {
        float v = (lane < 8) ? s_warp[lane] : 0.0f;
        #pragma unroll
        for (int off = 4; off; off >>= 1)
            v += __shfl_down_sync(0xffffffffu, v, off);
        if (lane == 0) atomicAdd(out, v * (1.0f / BATCH_N));
    }
}

extern "C" void kernel_launch(void* const* d_in, const int* in_sizes, int n_in,
                              void* d_out, int out_size)
{
    const float* pred = (const float*)d_in[0];
    const float* tgt  = (const float*)d_in[1];
    float* out = (float*)d_out;

    yolo_zero_out<<<1, 1>>>(out);
    yolo_loss_kernel<<<BATCH_N, 256>>>(pred, tgt, out);
}